// round 11
// baseline (speedup 1.0000x reference)
#include <cuda_runtime.h>
#include <math.h>
#include <stdint.h>

#define N_NODES 12800
#define N_EDGES 204800
#define DIM 16

typedef unsigned long long ull;

// ---------------- scratch (static device memory, no allocs) ----------------
__device__ float g_out[N_NODES * DIM];
__device__ float g_hs[N_EDGES * DIM];       // edge hidden, rank-sorted order
__device__ int   g_qs[N_EDGES];             // rank-sorted slot -> dst-sorted slot
__device__ float g_msg0[N_EDGES * DIM];     // message ping-pong (dst-sorted)
__device__ float g_msg1[N_EDGES * DIM];
__device__ int   g_src_cnt[N_NODES];        // zero at load; re-zeroed by k_scan
__device__ int   g_dst_cnt[N_NODES];        // zero at load; re-zeroed by k_scan
__device__ int   g_nid[N_NODES];            // rank -> node id (out-degree sorted)
__device__ int   g_roff[N_NODES + 1];       // rank -> edge offset (rank order)
__device__ int   g_dst_off[N_NODES + 1];    // node -> incoming msg offset
__device__ int   g_src_cur[N_NODES];
__device__ int   g_dst_cur[N_NODES];
__device__ float g_invdeg[N_NODES];

// ---------------- setup ----------------
// blocks [0,800): edge histograms; blocks [800,1600): lin0.
__global__ void k_hist(const float* __restrict__ x, const int* __restrict__ ei,
                       const float* __restrict__ l0w, const float* __restrict__ l0b) {
    int gb = blockIdx.x;
    if (gb < N_EDGES / 256) {
        int e = gb * 256 + threadIdx.x;
        atomicAdd(&g_src_cnt[ei[e]], 1);
        atomicAdd(&g_dst_cnt[ei[N_EDGES + e]], 1);
    } else {
        int i = (gb - N_EDGES / 256) * 256 + threadIdx.x;
        int n = i >> 4, k = i & 15;
        float acc = l0b[k];
#pragma unroll
        for (int c = 0; c < 3; ++c) acc += x[n * 3 + c] * l0w[k * 3 + c];
        g_out[i] = fmaxf(acc, 0.0f);
    }
}

// block 0: counting-sort nodes by out-degree -> g_nid/g_roff/g_src_cur;
//          re-zeroes src counts.
// block 1: exclusive scan of dst counts -> g_dst_off/g_dst_cur + invdeg;
//          re-zeroes dst counts.
__global__ void k_scan() {
    int tid = threadIdx.x, lane = tid & 31, wid = tid >> 5;
    if (blockIdx.x == 1) {
        const int PER = 13;
        int base = tid * PER;
        int c[PER];
        int local = 0;
#pragma unroll
        for (int i = 0; i < PER; ++i) {
            int idx = base + i;
            c[i] = (idx < N_NODES) ? g_dst_cnt[idx] : 0;
            local += c[i];
        }
        int incl = local;
#pragma unroll
        for (int s = 1; s < 32; s <<= 1) {
            int v = __shfl_up_sync(0xffffffffu, incl, s);
            if (lane >= s) incl += v;
        }
        __shared__ int wsum[32];
        if (lane == 31) wsum[wid] = incl;
        __syncthreads();
        if (wid == 0) {
            int v = wsum[lane], iv = v;
#pragma unroll
            for (int s = 1; s < 32; s <<= 1) {
                int t = __shfl_up_sync(0xffffffffu, iv, s);
                if (lane >= s) iv += t;
            }
            wsum[lane] = iv - v;
        }
        __syncthreads();
        int run = wsum[wid] + (incl - local);
#pragma unroll
        for (int i = 0; i < PER; ++i) {
            int idx = base + i;
            if (idx < N_NODES) {
                g_dst_off[idx] = run;
                g_dst_cur[idx] = run;
                g_invdeg[idx] = 1.0f / fmaxf((float)c[i], 1.0f);
                g_dst_cnt[idx] = 0;
                run += c[i];
            }
        }
        if (tid == 1023) g_dst_off[N_NODES] = run;
        return;
    }
    // ---- block 0: counting sort by out-degree ----
    __shared__ int hist[1024];
    __shared__ int nbase[1024];
    __shared__ int ebase[1024];
    __shared__ int wc[32], we[32];
    hist[tid] = 0;
    __syncthreads();
    for (int n = tid; n < N_NODES; n += 1024) {
        int d = g_src_cnt[n]; if (d > 1023) d = 1023;
        atomicAdd(&hist[d], 1);
    }
    __syncthreads();
    int c = hist[tid];
    int ec = c * tid;
    int ci = c, ei2 = ec;
#pragma unroll
    for (int s = 1; s < 32; s <<= 1) {
        int v = __shfl_up_sync(0xffffffffu, ci, s);
        int w2 = __shfl_up_sync(0xffffffffu, ei2, s);
        if (lane >= s) { ci += v; ei2 += w2; }
    }
    if (lane == 31) { wc[wid] = ci; we[wid] = ei2; }
    __syncthreads();
    if (wid == 0) {
        int v = wc[lane], iv = v, e = we[lane], ie = e;
#pragma unroll
        for (int s = 1; s < 32; s <<= 1) {
            int t1 = __shfl_up_sync(0xffffffffu, iv, s);
            int t2 = __shfl_up_sync(0xffffffffu, ie, s);
            if (lane >= s) { iv += t1; ie += t2; }
        }
        wc[lane] = iv - v; we[lane] = ie - e;
    }
    __syncthreads();
    nbase[tid] = wc[wid] + (ci - c);
    ebase[tid] = we[wid] + (ei2 - ec);
    hist[tid] = 0;                 // reuse as intra-bin cursor
    __syncthreads();
    for (int n = tid; n < N_NODES; n += 1024) {
        int d = g_src_cnt[n]; if (d > 1023) d = 1023;
        g_src_cnt[n] = 0;
        int t = atomicAdd(&hist[d], 1);
        int rank = nbase[d] + t;
        int eoff = ebase[d] + t * d;
        g_nid[rank] = n;
        g_roff[rank] = eoff;
        g_src_cur[n] = eoff;
    }
    if (tid == 0) g_roff[N_NODES] = N_EDGES;
}

// Per edge: place into rank-sorted slot p, record its dst-sorted slot q,
// compute edge hidden h = relu(ea @ nn1_w^T + nn1_b) directly into g_hs[p].
__global__ void k_scatter(const int* __restrict__ ei, const float* __restrict__ ea,
                          const float* __restrict__ n1w, const float* __restrict__ n1b) {
    int e = blockIdx.x * blockDim.x + threadIdx.x;
    if (e >= N_EDGES) return;
    int s = ei[e], d = ei[N_EDGES + e];
    int p = atomicAdd(&g_src_cur[s], 1);
    int q = atomicAdd(&g_dst_cur[d], 1);
    g_qs[p] = q;
    float4 a = __ldg((const float4*)&ea[e * 4]);
    float* hd = &g_hs[p * DIM];
#pragma unroll
    for (int j = 0; j < 16; j += 4) {
        float4 h;
        h.x = fmaxf(n1b[j + 0] + a.x * n1w[(j + 0) * 4] + a.y * n1w[(j + 0) * 4 + 1] +
                    a.z * n1w[(j + 0) * 4 + 2] + a.w * n1w[(j + 0) * 4 + 3], 0.0f);
        h.y = fmaxf(n1b[j + 1] + a.x * n1w[(j + 1) * 4] + a.y * n1w[(j + 1) * 4 + 1] +
                    a.z * n1w[(j + 1) * 4 + 2] + a.w * n1w[(j + 1) * 4 + 3], 0.0f);
        h.z = fmaxf(n1b[j + 2] + a.x * n1w[(j + 2) * 4] + a.y * n1w[(j + 2) * 4 + 1] +
                    a.z * n1w[(j + 2) * 4 + 2] + a.w * n1w[(j + 2) * 4 + 3], 0.0f);
        h.w = fmaxf(n1b[j + 3] + a.x * n1w[(j + 3) * 4] + a.y * n1w[(j + 3) * 4 + 1] +
                    a.z * n1w[(j + 3) * 4 + 2] + a.w * n1w[(j + 3) * 4 + 3], 0.0f);
        *(float4*)&hd[j] = h;
    }
}

// ---------------- fused per-round kernel (R3 mainloop + fused update) -------
// 256 threads = 16 rank-consecutive nodes x 16 lanes (lane owns one k).
// Phase 1 (r>0): contiguous read of prev msgs + mean + root + ReLU + GRU.
// Phase 2: P[k][j-pairs] in 8 f32x2 regs. Phase 3: per edge, h via __ldg
// (L1 broadcast when warm), dot, store to msg_w at dst-sorted slot.
__global__ void __launch_bounds__(256) k_round(
    const float* __restrict__ w2, const float* __restrict__ b2,
    const float* __restrict__ cr, const float* __restrict__ cb,
    const float* __restrict__ wih, const float* __restrict__ whh,
    const float* __restrict__ bih, const float* __restrict__ bhh,
    const float* __restrict__ msg_r, float* __restrict__ msg_w, int r) {
    __shared__ ull s_w2p[16 * 8 * 16];   // [d][jj][k], j-pairs packed: 16 KB
    __shared__ float s_b2[256];
    __shared__ float s_cr[256];
    __shared__ float s_wih[768];         // transposed [d][gate]
    __shared__ float s_whh[768];
    __shared__ float s_out[16][16];
    __shared__ float s_m[16][16];
    int tid = threadIdx.x;
    int k = tid & 15, g = tid >> 4;
    int rank = blockIdx.x * 16 + g;
    int n = g_nid[rank];

    for (int i = tid; i < 4096; i += 256) {
        int d = i >> 8, kk = (i >> 4) & 15, j = i & 15;
        ((float*)&s_w2p[(d * 8 + (j >> 1)) * 16 + kk])[j & 1] = w2[i];
    }
    s_b2[tid] = b2[tid];
    s_cr[tid] = cr[tid];
    for (int i = tid; i < 768; i += 256) {
        int rr = i >> 4, d = i & 15;
        s_wih[d * 48 + rr] = wih[i];
        s_whh[d * 48 + rr] = whh[i];
    }
    float hprev = g_out[n * DIM + k];
    s_out[g][k] = hprev;
    __syncthreads();

    if (r > 0) {
        // ---- fused update: mean(prev msgs) + root + ReLU + GRU ----
        int beg = g_dst_off[n], end = g_dst_off[n + 1];
        float a0 = 0.0f, a1 = 0.0f, a2 = 0.0f, a3 = 0.0f;
        int q = beg;
        for (; q + 3 < end; q += 4) {
            a0 += __ldg(&msg_r[(q + 0) * DIM + k]);
            a1 += __ldg(&msg_r[(q + 1) * DIM + k]);
            a2 += __ldg(&msg_r[(q + 2) * DIM + k]);
            a3 += __ldg(&msg_r[(q + 3) * DIM + k]);
        }
        for (; q < end; ++q) a0 += __ldg(&msg_r[q * DIM + k]);
        float acc = ((a0 + a1) + (a2 + a3)) * g_invdeg[n] + cb[k];
#pragma unroll
        for (int d = 0; d < DIM; ++d) acc += s_out[g][d] * s_cr[d * 16 + k];
        float m = fmaxf(acc, 0.0f);
        s_m[g][k] = m;
        __syncthreads();

        float gr = bih[k], gz = bih[k + 16], gn = bih[k + 32];
        float hr = bhh[k], hz = bhh[k + 16], hn = bhh[k + 32];
#pragma unroll
        for (int d = 0; d < DIM; ++d) {
            float md = s_m[g][d], hd = s_out[g][d];
            gr += md * s_wih[d * 48 + k];
            gz += md * s_wih[d * 48 + k + 16];
            gn += md * s_wih[d * 48 + k + 32];
            hr += hd * s_whh[d * 48 + k];
            hz += hd * s_whh[d * 48 + k + 16];
            hn += hd * s_whh[d * 48 + k + 32];
        }
        float rr = 1.0f / (1.0f + expf(-(gr + hr)));
        float zz = 1.0f / (1.0f + expf(-(gz + hz)));
        float nh = tanhf(gn + rr * hn);
        float hnew = (1.0f - zz) * nh + zz * hprev;
        __syncthreads();                 // all reads of s_out complete
        s_out[g][k] = hnew;
        g_out[n * DIM + k] = hnew;
        __syncthreads();
    }

    // ---- P-compute: P[k][j-pairs] in 8 f32x2 regs ----
    ull p2[8];
    float xb = 0.0f;
#pragma unroll
    for (int jj = 0; jj < 8; ++jj) p2[jj] = 0ull;
#pragma unroll
    for (int d = 0; d < 16; ++d) {
        float od = s_out[g][d];
        ull od2;
        asm("mov.b64 %0,{%1,%1};" : "=l"(od2) : "f"(od));
        xb += od * s_b2[d * 16 + k];
#pragma unroll
        for (int jj = 0; jj < 8; ++jj) {
            ull w = s_w2p[(d * 8 + jj) * 16 + k];
            asm("fma.rn.f32x2 %0,%1,%2,%0;" : "+l"(p2[jj]) : "l"(od2), "l"(w));
        }
    }

    // ---- edge mainloop (R3 style: direct ldg, no barriers) ----
    int beg = g_roff[rank], end = g_roff[rank + 1];
    const ulonglong2* hsp = (const ulonglong2*)g_hs;
    for (int i = beg; i < end; ++i) {
        int q = __ldg(&g_qs[i]);
        ulonglong2 A = __ldg(&hsp[i * 4 + 0]);
        ulonglong2 B = __ldg(&hsp[i * 4 + 1]);
        ulonglong2 C = __ldg(&hsp[i * 4 + 2]);
        ulonglong2 D = __ldg(&hsp[i * 4 + 3]);
        ull a0, a1;
        asm("mul.rn.f32x2 %0,%1,%2;" : "=l"(a0) : "l"(A.x), "l"(p2[0]));
        asm("fma.rn.f32x2 %0,%1,%2,%0;" : "+l"(a0) : "l"(A.y), "l"(p2[1]));
        asm("fma.rn.f32x2 %0,%1,%2,%0;" : "+l"(a0) : "l"(B.x), "l"(p2[2]));
        asm("fma.rn.f32x2 %0,%1,%2,%0;" : "+l"(a0) : "l"(B.y), "l"(p2[3]));
        asm("mul.rn.f32x2 %0,%1,%2;" : "=l"(a1) : "l"(C.x), "l"(p2[4]));
        asm("fma.rn.f32x2 %0,%1,%2,%0;" : "+l"(a1) : "l"(C.y), "l"(p2[5]));
        asm("fma.rn.f32x2 %0,%1,%2,%0;" : "+l"(a1) : "l"(D.x), "l"(p2[6]));
        asm("fma.rn.f32x2 %0,%1,%2,%0;" : "+l"(a1) : "l"(D.y), "l"(p2[7]));
        asm("add.rn.f32x2 %0,%0,%1;" : "+l"(a0) : "l"(a1));
        float lo, hi;
        asm("mov.b64 {%0,%1},%2;" : "=f"(lo), "=f"(hi) : "l"(a0));
        msg_w[q * DIM + k] = lo + hi + xb;   // 64B coalesced per 16-lane group
    }
}

// ---------------- final GRU-only kernel -> d_out ----------------
__global__ void k_fin(const float* __restrict__ msg_r,
                      const float* __restrict__ cr, const float* __restrict__ cb,
                      const float* __restrict__ wih, const float* __restrict__ whh,
                      const float* __restrict__ bih, const float* __restrict__ bhh,
                      float* __restrict__ outw) {
    __shared__ float s_cr[DIM * DIM];
    __shared__ float s_wih[DIM * 3 * DIM];
    __shared__ float s_whh[DIM * 3 * DIM];
    __shared__ float s_out[16][DIM];
    __shared__ float s_m[16][DIM];
    int tid = threadIdx.x;
    for (int i = tid; i < DIM * DIM; i += 256) s_cr[i] = cr[i];
    for (int i = tid; i < 3 * DIM * DIM; i += 256) {
        int r = i >> 4, d = i & 15;
        s_wih[d * 48 + r] = wih[i];
        s_whh[d * 48 + r] = whh[i];
    }
    int ln = tid >> 4, k = tid & 15;
    int n = blockIdx.x * 16 + ln;
    float hprev = g_out[n * DIM + k];
    s_out[ln][k] = hprev;
    __syncthreads();

    int beg = g_dst_off[n], end = g_dst_off[n + 1];
    float a0 = 0.0f, a1 = 0.0f, a2 = 0.0f, a3 = 0.0f;
    int q = beg;
    for (; q + 3 < end; q += 4) {
        a0 += __ldg(&msg_r[(q + 0) * DIM + k]);
        a1 += __ldg(&msg_r[(q + 1) * DIM + k]);
        a2 += __ldg(&msg_r[(q + 2) * DIM + k]);
        a3 += __ldg(&msg_r[(q + 3) * DIM + k]);
    }
    for (; q < end; ++q) a0 += __ldg(&msg_r[q * DIM + k]);
    float acc = ((a0 + a1) + (a2 + a3)) * g_invdeg[n] + cb[k];
#pragma unroll
    for (int d = 0; d < DIM; ++d) acc += s_out[ln][d] * s_cr[d * DIM + k];
    float m = fmaxf(acc, 0.0f);
    s_m[ln][k] = m;
    __syncthreads();

    float gr = bih[k], gz = bih[k + 16], gn = bih[k + 32];
    float hr = bhh[k], hz = bhh[k + 16], hn = bhh[k + 32];
#pragma unroll
    for (int d = 0; d < DIM; ++d) {
        float md = s_m[ln][d], hd = s_out[ln][d];
        gr += md * s_wih[d * 48 + k];
        gz += md * s_wih[d * 48 + k + 16];
        gn += md * s_wih[d * 48 + k + 32];
        hr += hd * s_whh[d * 48 + k];
        hz += hd * s_whh[d * 48 + k + 16];
        hn += hd * s_whh[d * 48 + k + 32];
    }
    float r = 1.0f / (1.0f + expf(-(gr + hr)));
    float z = 1.0f / (1.0f + expf(-(gz + hz)));
    float nh = tanhf(gn + r * hn);
    outw[n * DIM + k] = (1.0f - z) * nh + z * hprev;
}

// ---------------- host launcher ----------------
extern "C" void kernel_launch(void* const* d_in, const int* in_sizes, int n_in,
                              void* d_out, int out_size) {
    const float* x         = (const float*)d_in[0];
    const int*   ei        = (const int*)  d_in[1];
    const float* ea        = (const float*)d_in[2];
    const float* lin0_w    = (const float*)d_in[3];
    const float* lin0_b    = (const float*)d_in[4];
    const float* nn1_w     = (const float*)d_in[5];
    const float* nn1_b     = (const float*)d_in[6];
    const float* nn2_w     = (const float*)d_in[7];
    const float* nn2_b     = (const float*)d_in[8];
    const float* conv_root = (const float*)d_in[9];
    const float* conv_bias = (const float*)d_in[10];
    const float* w_ih      = (const float*)d_in[11];
    const float* w_hh      = (const float*)d_in[12];
    const float* b_ih      = (const float*)d_in[13];
    const float* b_hh      = (const float*)d_in[14];

    float *m0 = nullptr, *m1 = nullptr;
    cudaGetSymbolAddress((void**)&m0, g_msg0);
    cudaGetSymbolAddress((void**)&m1, g_msg1);

    k_hist<<<N_EDGES / 256 + (N_NODES * DIM) / 256, 256>>>(x, ei, lin0_w, lin0_b);
    k_scan<<<2, 1024>>>();
    k_scatter<<<(N_EDGES + 255) / 256, 256>>>(ei, ea, nn1_w, nn1_b);

    for (int r = 0; r < 6; ++r) {
        const float* mr = ((r - 1) & 1) ? m1 : m0;   // buffer written by r-1
        float* mw = (r & 1) ? m1 : m0;
        k_round<<<N_NODES / 16, 256>>>(nn2_w, nn2_b, conv_root, conv_bias,
                                       w_ih, w_hh, b_ih, b_hh, mr, mw, r);
    }
    k_fin<<<N_NODES / 16, 256>>>(m1, conv_root, conv_bias, w_ih, w_hh,
                                 b_ih, b_hh, (float*)d_out);
}

// round 12
// speedup vs baseline: 1.2457x; 1.2457x over previous
#include <cuda_runtime.h>
#include <math.h>
#include <stdint.h>

#define N_NODES 12800
#define N_EDGES 204800
#define DIM 16

typedef unsigned long long ull;

// ---------------- scratch (static device memory, no allocs) ----------------
__device__ float g_out[N_NODES * DIM];
__device__ float g_hs[N_EDGES * DIM];       // edge hidden, rank-sorted order
__device__ int   g_qs[N_EDGES];             // rank-sorted slot -> dst-sorted slot
__device__ float g_msg[N_EDGES * DIM];      // messages (dst-sorted)
__device__ int   g_src_cnt[N_NODES];        // zero at load; re-zeroed by k_scan
__device__ int   g_dst_cnt[N_NODES];        // zero at load; re-zeroed by k_scan
__device__ int   g_nid[N_NODES];            // rank -> node id (out-degree sorted)
__device__ int   g_roff[N_NODES + 1];       // rank -> edge offset
__device__ int   g_dst_off[N_NODES + 1];    // node -> incoming msg offset
__device__ int   g_src_cur[N_NODES];
__device__ int   g_dst_cur[N_NODES];
__device__ float g_invdeg[N_NODES];

// ---------------- setup ----------------
// blocks [0,800): edge histograms; blocks [800,1600): lin0.
__global__ void k_hist(const float* __restrict__ x, const int* __restrict__ ei,
                       const float* __restrict__ l0w, const float* __restrict__ l0b) {
    int gb = blockIdx.x;
    if (gb < N_EDGES / 256) {
        int e = gb * 256 + threadIdx.x;
        atomicAdd(&g_src_cnt[ei[e]], 1);
        atomicAdd(&g_dst_cnt[ei[N_EDGES + e]], 1);
    } else {
        int i = (gb - N_EDGES / 256) * 256 + threadIdx.x;
        int n = i >> 4, k = i & 15;
        float acc = l0b[k];
#pragma unroll
        for (int c = 0; c < 3; ++c) acc += x[n * 3 + c] * l0w[k * 3 + c];
        g_out[i] = fmaxf(acc, 0.0f);
    }
}

// block 0: counting-sort nodes by out-degree -> g_nid/g_roff/g_src_cur.
// block 1: exclusive scan of dst counts -> g_dst_off/g_dst_cur + invdeg.
// Both re-zero their count arrays for the next kernel_launch call.
__global__ void k_scan() {
    int tid = threadIdx.x, lane = tid & 31, wid = tid >> 5;
    if (blockIdx.x == 1) {
        const int PER = 13;
        int base = tid * PER;
        int c[PER];
        int local = 0;
#pragma unroll
        for (int i = 0; i < PER; ++i) {
            int idx = base + i;
            c[i] = (idx < N_NODES) ? g_dst_cnt[idx] : 0;
            local += c[i];
        }
        int incl = local;
#pragma unroll
        for (int s = 1; s < 32; s <<= 1) {
            int v = __shfl_up_sync(0xffffffffu, incl, s);
            if (lane >= s) incl += v;
        }
        __shared__ int wsum[32];
        if (lane == 31) wsum[wid] = incl;
        __syncthreads();
        if (wid == 0) {
            int v = wsum[lane], iv = v;
#pragma unroll
            for (int s = 1; s < 32; s <<= 1) {
                int t = __shfl_up_sync(0xffffffffu, iv, s);
                if (lane >= s) iv += t;
            }
            wsum[lane] = iv - v;
        }
        __syncthreads();
        int run = wsum[wid] + (incl - local);
#pragma unroll
        for (int i = 0; i < PER; ++i) {
            int idx = base + i;
            if (idx < N_NODES) {
                g_dst_off[idx] = run;
                g_dst_cur[idx] = run;
                g_invdeg[idx] = 1.0f / fmaxf((float)c[i], 1.0f);
                g_dst_cnt[idx] = 0;
                run += c[i];
            }
        }
        if (tid == 1023) g_dst_off[N_NODES] = run;
        return;
    }
    // ---- block 0: counting sort by out-degree ----
    __shared__ int hist[1024];
    __shared__ int nbase[1024];
    __shared__ int ebase[1024];
    __shared__ int wc[32], we[32];
    hist[tid] = 0;
    __syncthreads();
    for (int n = tid; n < N_NODES; n += 1024) {
        int d = g_src_cnt[n]; if (d > 1023) d = 1023;
        atomicAdd(&hist[d], 1);
    }
    __syncthreads();
    int c = hist[tid];
    int ec = c * tid;
    int ci = c, ei2 = ec;
#pragma unroll
    for (int s = 1; s < 32; s <<= 1) {
        int v = __shfl_up_sync(0xffffffffu, ci, s);
        int w2 = __shfl_up_sync(0xffffffffu, ei2, s);
        if (lane >= s) { ci += v; ei2 += w2; }
    }
    if (lane == 31) { wc[wid] = ci; we[wid] = ei2; }
    __syncthreads();
    if (wid == 0) {
        int v = wc[lane], iv = v, e = we[lane], ie = e;
#pragma unroll
        for (int s = 1; s < 32; s <<= 1) {
            int t1 = __shfl_up_sync(0xffffffffu, iv, s);
            int t2 = __shfl_up_sync(0xffffffffu, ie, s);
            if (lane >= s) { iv += t1; ie += t2; }
        }
        wc[lane] = iv - v; we[lane] = ie - e;
    }
    __syncthreads();
    nbase[tid] = wc[wid] + (ci - c);
    ebase[tid] = we[wid] + (ei2 - ec);
    hist[tid] = 0;                 // reuse as intra-bin cursor
    __syncthreads();
    for (int n = tid; n < N_NODES; n += 1024) {
        int d = g_src_cnt[n]; if (d > 1023) d = 1023;
        g_src_cnt[n] = 0;
        int t = atomicAdd(&hist[d], 1);
        int rank = nbase[d] + t;
        int eoff = ebase[d] + t * d;
        g_nid[rank] = n;
        g_roff[rank] = eoff;
        g_src_cur[n] = eoff;
    }
    if (tid == 0) g_roff[N_NODES] = N_EDGES;
}

// Per edge: place into rank-sorted slot p, record its dst-sorted slot q,
// compute edge hidden h = relu(ea @ nn1_w^T + nn1_b) directly into g_hs[p].
__global__ void k_scatter(const int* __restrict__ ei, const float* __restrict__ ea,
                          const float* __restrict__ n1w, const float* __restrict__ n1b) {
    int e = blockIdx.x * blockDim.x + threadIdx.x;
    if (e >= N_EDGES) return;
    int s = ei[e], d = ei[N_EDGES + e];
    int p = atomicAdd(&g_src_cur[s], 1);
    int q = atomicAdd(&g_dst_cur[d], 1);
    g_qs[p] = q;
    float4 a = __ldg((const float4*)&ea[e * 4]);
    float* hd = &g_hs[p * DIM];
#pragma unroll
    for (int j = 0; j < 16; j += 4) {
        float4 h;
        h.x = fmaxf(n1b[j + 0] + a.x * n1w[(j + 0) * 4] + a.y * n1w[(j + 0) * 4 + 1] +
                    a.z * n1w[(j + 0) * 4 + 2] + a.w * n1w[(j + 0) * 4 + 3], 0.0f);
        h.y = fmaxf(n1b[j + 1] + a.x * n1w[(j + 1) * 4] + a.y * n1w[(j + 1) * 4 + 1] +
                    a.z * n1w[(j + 1) * 4 + 2] + a.w * n1w[(j + 1) * 4 + 3], 0.0f);
        h.z = fmaxf(n1b[j + 2] + a.x * n1w[(j + 2) * 4] + a.y * n1w[(j + 2) * 4 + 1] +
                    a.z * n1w[(j + 2) * 4 + 2] + a.w * n1w[(j + 2) * 4 + 3], 0.0f);
        h.w = fmaxf(n1b[j + 3] + a.x * n1w[(j + 3) * 4] + a.y * n1w[(j + 3) * 4 + 1] +
                    a.z * n1w[(j + 3) * 4 + 2] + a.w * n1w[(j + 3) * 4 + 3], 0.0f);
        *(float4*)&hd[j] = h;
    }
}

// ---------------- per-round kernels (R3 architecture, rank-ordered) --------
// k_msg: 128 threads = 32 RANKS x 4 lanes. Ranks in a warp are consecutive
// (same out-degree) -> near-zero intra-warp divergence. Each lane owns
// k = l*4..l*4+3, holds P as 32 packed f32x2 regs, streams its rank's edges.
__global__ void __launch_bounds__(128) k_msg(const float* __restrict__ w2,
                                             const float* __restrict__ b2) {
    __shared__ ull s_w2p[16 * 8 * 16];   // [d][jj][k], j-pairs packed, 16KB
    __shared__ float s_b2[256];          // [d][k]
    __shared__ float s_out[32][17];
    int tid = threadIdx.x;
    for (int i = tid; i < 4096; i += 128) {
        int d = i >> 8, k = (i >> 4) & 15, j = i & 15;
        ((float*)&s_w2p[(d * 8 + (j >> 1)) * 16 + k])[j & 1] = w2[i];
    }
    for (int i = tid; i < 256; i += 128) s_b2[i] = b2[i];
    int rb = blockIdx.x * 32;
    for (int i = tid; i < 32 * DIM; i += 128) {
        int node = g_nid[rb + (i >> 4)];
        s_out[i >> 4][i & 15] = g_out[node * DIM + (i & 15)];
    }
    __syncthreads();

    int l = tid & 3;                     // k-quad index
    int g = tid >> 2;                    // rank within block
    int rank = rb + g;

    ull p2[32];                          // [kk][jj]
    float xb[4];
#pragma unroll
    for (int i = 0; i < 32; ++i) p2[i] = 0ull;
#pragma unroll
    for (int kk = 0; kk < 4; ++kk) xb[kk] = 0.0f;
#pragma unroll
    for (int d = 0; d < 16; ++d) {
        float od = s_out[g][d];
        ull od2;
        asm("mov.b64 %0,{%1,%1};" : "=l"(od2) : "f"(od));
#pragma unroll
        for (int kk = 0; kk < 4; ++kk) {
            int k = l * 4 + kk;
            xb[kk] += od * s_b2[d * 16 + k];
#pragma unroll
            for (int jj = 0; jj < 8; ++jj) {
                ull w = s_w2p[(d * 8 + jj) * 16 + k];
                asm("fma.rn.f32x2 %0,%1,%2,%0;" : "+l"(p2[kk * 8 + jj]) : "l"(od2), "l"(w));
            }
        }
    }

    int beg = g_roff[rank], end = g_roff[rank + 1];
    const ulonglong2* hsp = (const ulonglong2*)g_hs;
    for (int i = beg; i < end; ++i) {
        int q = __ldg(&g_qs[i]);
        ulonglong2 A = hsp[i * 4 + 0], B = hsp[i * 4 + 1];
        ulonglong2 C = hsp[i * 4 + 2], D = hsp[i * 4 + 3];
        float4 m4;
        float* mm = (float*)&m4;
#pragma unroll
        for (int kk = 0; kk < 4; ++kk) {
            ull acc;
            asm("mul.rn.f32x2 %0,%1,%2;" : "=l"(acc) : "l"(A.x), "l"(p2[kk * 8 + 0]));
            asm("fma.rn.f32x2 %0,%1,%2,%0;" : "+l"(acc) : "l"(A.y), "l"(p2[kk * 8 + 1]));
            asm("fma.rn.f32x2 %0,%1,%2,%0;" : "+l"(acc) : "l"(B.x), "l"(p2[kk * 8 + 2]));
            asm("fma.rn.f32x2 %0,%1,%2,%0;" : "+l"(acc) : "l"(B.y), "l"(p2[kk * 8 + 3]));
            asm("fma.rn.f32x2 %0,%1,%2,%0;" : "+l"(acc) : "l"(C.x), "l"(p2[kk * 8 + 4]));
            asm("fma.rn.f32x2 %0,%1,%2,%0;" : "+l"(acc) : "l"(C.y), "l"(p2[kk * 8 + 5]));
            asm("fma.rn.f32x2 %0,%1,%2,%0;" : "+l"(acc) : "l"(D.x), "l"(p2[kk * 8 + 6]));
            asm("fma.rn.f32x2 %0,%1,%2,%0;" : "+l"(acc) : "l"(D.y), "l"(p2[kk * 8 + 7]));
            float lo, hi;
            asm("mov.b64 {%0,%1},%2;" : "=f"(lo), "=f"(hi) : "l"(acc));
            mm[kk] = lo + hi + xb[kk];
        }
        ((float4*)g_msg)[q * 4 + l] = m4;   // 64B per edge
    }
}

// k_upd: contiguous message mean + root matmul + ReLU + GRU (natural order).
__global__ void k_upd(const float* __restrict__ cr, const float* __restrict__ cb,
                      const float* __restrict__ wih, const float* __restrict__ whh,
                      const float* __restrict__ bih, const float* __restrict__ bhh,
                      float* __restrict__ outw) {
    __shared__ float s_cr[DIM * DIM];
    __shared__ float s_wih[DIM * 3 * DIM];   // transposed [d][gate]
    __shared__ float s_whh[DIM * 3 * DIM];
    __shared__ float s_out[16][DIM];
    __shared__ float s_m[16][DIM];
    int tid = threadIdx.x;
    for (int i = tid; i < DIM * DIM; i += 256) s_cr[i] = cr[i];
    for (int i = tid; i < 3 * DIM * DIM; i += 256) {
        int r = i >> 4, d = i & 15;
        s_wih[d * 48 + r] = wih[i];
        s_whh[d * 48 + r] = whh[i];
    }
    int ln = tid >> 4, k = tid & 15;
    int n = blockIdx.x * 16 + ln;
    float hprev = g_out[n * DIM + k];
    s_out[ln][k] = hprev;
    __syncthreads();

    int beg = g_dst_off[n], end = g_dst_off[n + 1];
    float a0 = 0.0f, a1 = 0.0f, a2 = 0.0f, a3 = 0.0f;
    int q = beg;
    for (; q + 3 < end; q += 4) {
        a0 += __ldg(&g_msg[(q + 0) * DIM + k]);
        a1 += __ldg(&g_msg[(q + 1) * DIM + k]);
        a2 += __ldg(&g_msg[(q + 2) * DIM + k]);
        a3 += __ldg(&g_msg[(q + 3) * DIM + k]);
    }
    for (; q < end; ++q) a0 += __ldg(&g_msg[q * DIM + k]);
    float acc = ((a0 + a1) + (a2 + a3)) * g_invdeg[n] + cb[k];
#pragma unroll
    for (int d = 0; d < DIM; ++d) acc += s_out[ln][d] * s_cr[d * DIM + k];
    float m = fmaxf(acc, 0.0f);
    s_m[ln][k] = m;
    __syncthreads();

    float gr = bih[k], gz = bih[k + 16], gn = bih[k + 32];
    float hr = bhh[k], hz = bhh[k + 16], hn = bhh[k + 32];
#pragma unroll
    for (int d = 0; d < DIM; ++d) {
        float md = s_m[ln][d], hd = s_out[ln][d];
        gr += md * s_wih[d * 48 + k];
        gz += md * s_wih[d * 48 + k + 16];
        gn += md * s_wih[d * 48 + k + 32];
        hr += hd * s_whh[d * 48 + k];
        hz += hd * s_whh[d * 48 + k + 16];
        hn += hd * s_whh[d * 48 + k + 32];
    }
    float r = 1.0f / (1.0f + expf(-(gr + hr)));
    float z = 1.0f / (1.0f + expf(-(gz + hz)));
    float nh = tanhf(gn + r * hn);
    outw[n * DIM + k] = (1.0f - z) * nh + z * hprev;
}

// ---------------- host launcher ----------------
extern "C" void kernel_launch(void* const* d_in, const int* in_sizes, int n_in,
                              void* d_out, int out_size) {
    const float* x         = (const float*)d_in[0];
    const int*   ei        = (const int*)  d_in[1];
    const float* ea        = (const float*)d_in[2];
    const float* lin0_w    = (const float*)d_in[3];
    const float* lin0_b    = (const float*)d_in[4];
    const float* nn1_w     = (const float*)d_in[5];
    const float* nn1_b     = (const float*)d_in[6];
    const float* nn2_w     = (const float*)d_in[7];
    const float* nn2_b     = (const float*)d_in[8];
    const float* conv_root = (const float*)d_in[9];
    const float* conv_bias = (const float*)d_in[10];
    const float* w_ih      = (const float*)d_in[11];
    const float* w_hh      = (const float*)d_in[12];
    const float* b_ih      = (const float*)d_in[13];
    const float* b_hh      = (const float*)d_in[14];

    float* outp = nullptr;
    cudaGetSymbolAddress((void**)&outp, g_out);

    k_hist<<<N_EDGES / 256 + (N_NODES * DIM) / 256, 256>>>(x, ei, lin0_w, lin0_b);
    k_scan<<<2, 1024>>>();
    k_scatter<<<(N_EDGES + 255) / 256, 256>>>(ei, ea, nn1_w, nn1_b);

    for (int r = 0; r < 6; ++r) {
        k_msg<<<N_NODES / 32, 128>>>(nn2_w, nn2_b);
        k_upd<<<N_NODES / 16, 256>>>(conv_root, conv_bias, w_ih, w_hh, b_ih, b_hh,
                                     r == 5 ? (float*)d_out : outp);
    }
}